// round 2
// baseline (speedup 1.0000x reference)
#include <cuda_runtime.h>

#define BB 4
#define TT 2048
#define DD 512
#define HH 8
#define HS 64

// Scratch (allocation-free rule: __device__ globals)
__device__ float g_q[BB*HH*TT*HS];     // [B,H,T,HS]
__device__ float g_k[BB*HH*TT*HS];
__device__ float g_v[BB*HH*TT*HS];
__device__ float g_attn[BB*TT*DD];     // [B,T,D] (heads concatenated)

#define BK 32
#define XS_LD 68   // padded row (68*4B = 272B, 16B-aligned rows, reduces STS conflicts)

// ---------------------------------------------------------------------------
// Kernel 1: QKV projections.  out[b,h,t,e] = sum_d x[b,t,d] * W[h,d,e]
// grid: (BT/64=128, H=8, 3[q,k,v]), block 256. 64x64 tile, BK=32, 4x4 microtile.
// ---------------------------------------------------------------------------
__global__ __launch_bounds__(256) void qkv_proj_kernel(
    const float* __restrict__ x,
    const float* __restrict__ Wq,
    const float* __restrict__ Wk,
    const float* __restrict__ Wv)
{
    __shared__ float xs[BK][XS_LD];   // k-major: xs[k][m]
    __shared__ float ws[BK][64];      // k-major: ws[k][e]

    const int tid = threadIdx.x;
    const int tx = tid & 15;          // 0..15 -> N (cols, *4)
    const int ty = tid >> 4;          // 0..15 -> M (rows, *4)
    const int m0 = blockIdx.x * 64;
    const int h  = blockIdx.y;
    const int wsel = blockIdx.z;

    const float* W = (wsel == 0) ? Wq : (wsel == 1 ? Wk : Wv);
    W += (size_t)h * DD * HS;
    float* out = (wsel == 0) ? g_q : (wsel == 1 ? g_k : g_v);

    float acc[4][4];
    #pragma unroll
    for (int i = 0; i < 4; i++)
        #pragma unroll
        for (int j = 0; j < 4; j++) acc[i][j] = 0.f;

    for (int k0 = 0; k0 < DD; k0 += BK) {
        __syncthreads();
        // load x tile 64x32, store transposed into xs[k][m]
        #pragma unroll
        for (int it = 0; it < 2; it++) {
            int idx = tid + it * 256;              // 0..511 float4 slots
            int r = idx >> 3, c4 = idx & 7;
            float4 v = *(const float4*)(x + (size_t)(m0 + r) * DD + k0 + c4 * 4);
            xs[c4*4+0][r] = v.x;
            xs[c4*4+1][r] = v.y;
            xs[c4*4+2][r] = v.z;
            xs[c4*4+3][r] = v.w;
        }
        // load W tile 32x64 (already k-major), direct copy
        #pragma unroll
        for (int it = 0; it < 2; it++) {
            int idx = tid + it * 256;
            int kk = idx >> 4, e4 = idx & 15;
            *(float4*)&ws[kk][e4*4] =
                *(const float4*)(W + (size_t)(k0 + kk) * HS + e4 * 4);
        }
        __syncthreads();
        #pragma unroll
        for (int kk = 0; kk < BK; kk++) {
            float4 a4 = *(const float4*)&xs[kk][ty*4];
            float4 b4 = *(const float4*)&ws[kk][tx*4];
            float av[4] = {a4.x, a4.y, a4.z, a4.w};
            float bv[4] = {b4.x, b4.y, b4.z, b4.w};
            #pragma unroll
            for (int i = 0; i < 4; i++)
                #pragma unroll
                for (int j = 0; j < 4; j++)
                    acc[i][j] += av[i] * bv[j];
        }
    }

    #pragma unroll
    for (int i = 0; i < 4; i++) {
        int m = m0 + ty * 4 + i;           // global row over B*T
        int bb = m >> 11;                  // m / T  (T=2048)
        int t  = m & (TT - 1);
        float4 o = make_float4(acc[i][0], acc[i][1], acc[i][2], acc[i][3]);
        *(float4*)(out + ((size_t)(bb * HH + h) * TT + t) * HS + tx * 4) = o;
    }
}

// ---------------------------------------------------------------------------
// Kernel 2: flash attention (fp32, online softmax).
// grid: (T/128=16, B*H=32), block 128. One thread = one query.
// q[64] + acc[64] in registers; K/V streamed via smem in 16-key tiles.
// ---------------------------------------------------------------------------
#define KT 16

__global__ __launch_bounds__(128) void attn_kernel()
{
    __shared__ float4 ks4[KT * 16];   // KT keys x 64 floats
    __shared__ float4 vs4[KT * 16];

    const int tid = threadIdx.x;
    const int bh  = blockIdx.y;            // b*H + h
    const int qt  = blockIdx.x * 128 + tid;

    const float SCALE = 0.125f;            // 1/sqrt(64)

    // load query row into registers
    float q[64];
    {
        const float4* qg = (const float4*)(g_q + ((size_t)bh * TT + qt) * HS);
        #pragma unroll
        for (int e4 = 0; e4 < 16; e4++) {
            float4 v = qg[e4];
            q[e4*4+0] = v.x; q[e4*4+1] = v.y; q[e4*4+2] = v.z; q[e4*4+3] = v.w;
        }
    }

    float acc[64];
    #pragma unroll
    for (int e = 0; e < 64; e++) acc[e] = 0.f;
    float mrun = -1e30f;
    float lsum = 0.f;

    const float4* kg = (const float4*)(g_k + (size_t)bh * TT * HS);
    const float4* vg = (const float4*)(g_v + (size_t)bh * TT * HS);

    for (int t0 = 0; t0 < TT; t0 += KT) {
        __syncthreads();
        #pragma unroll
        for (int i = tid; i < KT * 16; i += 128) {
            ks4[i] = kg[t0 * 16 + i];
            vs4[i] = vg[t0 * 16 + i];
        }
        __syncthreads();

        // scores for this key tile
        float s[KT];
        float tmax = -1e30f;
        #pragma unroll
        for (int j = 0; j < KT; j++) {
            float s0 = 0.f, s1 = 0.f, s2 = 0.f, s3 = 0.f;
            #pragma unroll
            for (int e4 = 0; e4 < 16; e4++) {
                float4 kv = ks4[j * 16 + e4];
                s0 += q[e4*4+0] * kv.x;
                s1 += q[e4*4+1] * kv.y;
                s2 += q[e4*4+2] * kv.z;
                s3 += q[e4*4+3] * kv.w;
            }
            s[j] = ((s0 + s1) + (s2 + s3)) * SCALE;
            tmax = fmaxf(tmax, s[j]);
        }

        float mnew = fmaxf(mrun, tmax);
        float corr = __expf(mrun - mnew);
        lsum *= corr;
        #pragma unroll
        for (int e = 0; e < 64; e++) acc[e] *= corr;

        #pragma unroll
        for (int j = 0; j < KT; j++) {
            float p = __expf(s[j] - mnew);
            lsum += p;
            #pragma unroll
            for (int e4 = 0; e4 < 16; e4++) {
                float4 vv = vs4[j * 16 + e4];
                acc[e4*4+0] += p * vv.x;
                acc[e4*4+1] += p * vv.y;
                acc[e4*4+2] += p * vv.z;
                acc[e4*4+3] += p * vv.w;
            }
        }
        mrun = mnew;
    }

    // normalize + write to [B,T,D] concat-head layout
    float inv = 1.f / lsum;
    const int bb = bh / HH;
    const int hh = bh % HH;
    float* og = g_attn + ((size_t)bb * TT + qt) * DD + hh * HS;
    #pragma unroll
    for (int e4 = 0; e4 < 16; e4++) {
        float4 o = make_float4(acc[e4*4+0] * inv, acc[e4*4+1] * inv,
                               acc[e4*4+2] * inv, acc[e4*4+3] * inv);
        *(float4*)(og + e4 * 4) = o;
    }
}

// ---------------------------------------------------------------------------
// Kernel 3: output projection.  out = attn[BT,D] @ Wo[D,D] + bo
// grid: (BT/64=128, D/64=8), block 256. Same tiling as kernel 1.
// ---------------------------------------------------------------------------
__global__ __launch_bounds__(256) void oproj_kernel(
    const float* __restrict__ Wo,
    const float* __restrict__ bo,
    float* __restrict__ out)
{
    __shared__ float xs[BK][XS_LD];
    __shared__ float ws[BK][64];

    const int tid = threadIdx.x;
    const int tx = tid & 15;
    const int ty = tid >> 4;
    const int m0 = blockIdx.x * 64;
    const int n0 = blockIdx.y * 64;

    float acc[4][4];
    #pragma unroll
    for (int i = 0; i < 4; i++)
        #pragma unroll
        for (int j = 0; j < 4; j++) acc[i][j] = 0.f;

    for (int k0 = 0; k0 < DD; k0 += BK) {
        __syncthreads();
        #pragma unroll
        for (int it = 0; it < 2; it++) {
            int idx = tid + it * 256;
            int r = idx >> 3, c4 = idx & 7;
            float4 v = *(const float4*)(g_attn + (size_t)(m0 + r) * DD + k0 + c4 * 4);
            xs[c4*4+0][r] = v.x;
            xs[c4*4+1][r] = v.y;
            xs[c4*4+2][r] = v.z;
            xs[c4*4+3][r] = v.w;
        }
        #pragma unroll
        for (int it = 0; it < 2; it++) {
            int idx = tid + it * 256;
            int kk = idx >> 4, e4 = idx & 15;
            *(float4*)&ws[kk][e4*4] =
                *(const float4*)(Wo + (size_t)(k0 + kk) * DD + n0 + e4 * 4);
        }
        __syncthreads();
        #pragma unroll
        for (int kk = 0; kk < BK; kk++) {
            float4 a4 = *(const float4*)&xs[kk][ty*4];
            float4 b4 = *(const float4*)&ws[kk][tx*4];
            float av[4] = {a4.x, a4.y, a4.z, a4.w};
            float bv[4] = {b4.x, b4.y, b4.z, b4.w};
            #pragma unroll
            for (int i = 0; i < 4; i++)
                #pragma unroll
                for (int j = 0; j < 4; j++)
                    acc[i][j] += av[i] * bv[j];
        }
    }

    float4 bias = *(const float4*)(bo + n0 + tx * 4);
    #pragma unroll
    for (int i = 0; i < 4; i++) {
        int m = m0 + ty * 4 + i;
        float4 o = make_float4(acc[i][0] + bias.x, acc[i][1] + bias.y,
                               acc[i][2] + bias.z, acc[i][3] + bias.w);
        *(float4*)(out + (size_t)m * DD + n0 + tx * 4) = o;
    }
}

// ---------------------------------------------------------------------------
extern "C" void kernel_launch(void* const* d_in, const int* in_sizes, int n_in,
                              void* d_out, int out_size)
{
    const float* x  = (const float*)d_in[0];
    const float* Wq = (const float*)d_in[1];
    const float* Wk = (const float*)d_in[2];
    const float* Wv = (const float*)d_in[3];
    const float* Wo = (const float*)d_in[4];
    const float* bo = (const float*)d_in[5];
    float* out = (float*)d_out;

    dim3 g1((BB * TT) / 64, HH, 3);
    qkv_proj_kernel<<<g1, 256>>>(x, Wq, Wk, Wv);

    dim3 g2(TT / 128, BB * HH);
    attn_kernel<<<g2, 128>>>();

    dim3 g3((BB * TT) / 64, DD / 64);
    oproj_kernel<<<g3, 256>>>(Wo, bo, out);
}

// round 3
// speedup vs baseline: 2.2868x; 2.2868x over previous
#include <cuda_runtime.h>
#include <cstdint>

#define BB 4
#define TT 2048
#define DD 512
#define HH 8
#define HS 64

// Scratch (allocation-free rule: __device__ globals)
__device__ float g_q[BB*HH*TT*HS];     // [B,H,T,HS]
__device__ float g_k[BB*HH*TT*HS];
__device__ float g_v[BB*HH*TT*HS];
__device__ float g_attn[BB*TT*DD];     // [B,T,D] (heads concatenated)

#define BK 32
#define XS_LD 68

// ---------------------------------------------------------------------------
// helpers
// ---------------------------------------------------------------------------
__device__ __forceinline__ float to_tf32(float x) {
    uint32_t u;
    asm("cvt.rna.tf32.f32 %0, %1;" : "=r"(u) : "f"(x));
    return __uint_as_float(u);
}

__device__ __forceinline__ void mma16n8k8(float c[4], const float a[4],
                                          float b0, float b1) {
    asm volatile(
        "mma.sync.aligned.m16n8k8.row.col.f32.tf32.tf32.f32 "
        "{%0,%1,%2,%3}, {%4,%5,%6,%7}, {%8,%9}, {%0,%1,%2,%3};"
        : "+f"(c[0]), "+f"(c[1]), "+f"(c[2]), "+f"(c[3])
        : "r"(__float_as_uint(a[0])), "r"(__float_as_uint(a[1])),
          "r"(__float_as_uint(a[2])), "r"(__float_as_uint(a[3])),
          "r"(__float_as_uint(b0)),  "r"(__float_as_uint(b1)));
}

// ---------------------------------------------------------------------------
// Kernel 1: QKV projections (unchanged from R0 baseline).
// ---------------------------------------------------------------------------
__global__ __launch_bounds__(256) void qkv_proj_kernel(
    const float* __restrict__ x,
    const float* __restrict__ Wq,
    const float* __restrict__ Wk,
    const float* __restrict__ Wv)
{
    __shared__ float xs[BK][XS_LD];
    __shared__ float ws[BK][64];

    const int tid = threadIdx.x;
    const int tx = tid & 15;
    const int ty = tid >> 4;
    const int m0 = blockIdx.x * 64;
    const int h  = blockIdx.y;
    const int wsel = blockIdx.z;

    const float* W = (wsel == 0) ? Wq : (wsel == 1 ? Wk : Wv);
    W += (size_t)h * DD * HS;
    float* out = (wsel == 0) ? g_q : (wsel == 1 ? g_k : g_v);

    float acc[4][4];
    #pragma unroll
    for (int i = 0; i < 4; i++)
        #pragma unroll
        for (int j = 0; j < 4; j++) acc[i][j] = 0.f;

    for (int k0 = 0; k0 < DD; k0 += BK) {
        __syncthreads();
        #pragma unroll
        for (int it = 0; it < 2; it++) {
            int idx = tid + it * 256;
            int r = idx >> 3, c4 = idx & 7;
            float4 v = *(const float4*)(x + (size_t)(m0 + r) * DD + k0 + c4 * 4);
            xs[c4*4+0][r] = v.x;
            xs[c4*4+1][r] = v.y;
            xs[c4*4+2][r] = v.z;
            xs[c4*4+3][r] = v.w;
        }
        #pragma unroll
        for (int it = 0; it < 2; it++) {
            int idx = tid + it * 256;
            int kk = idx >> 4, e4 = idx & 15;
            *(float4*)&ws[kk][e4*4] =
                *(const float4*)(W + (size_t)(k0 + kk) * HS + e4 * 4);
        }
        __syncthreads();
        #pragma unroll
        for (int kk = 0; kk < BK; kk++) {
            float4 a4 = *(const float4*)&xs[kk][ty*4];
            float4 b4 = *(const float4*)&ws[kk][tx*4];
            float av[4] = {a4.x, a4.y, a4.z, a4.w};
            float bv[4] = {b4.x, b4.y, b4.z, b4.w};
            #pragma unroll
            for (int i = 0; i < 4; i++)
                #pragma unroll
                for (int j = 0; j < 4; j++)
                    acc[i][j] += av[i] * bv[j];
        }
    }

    #pragma unroll
    for (int i = 0; i < 4; i++) {
        int m = m0 + ty * 4 + i;
        int bb = m >> 11;
        int t  = m & (TT - 1);
        float4 o = make_float4(acc[i][0], acc[i][1], acc[i][2], acc[i][3]);
        *(float4*)(out + ((size_t)(bb * HH + h) * TT + t) * HS + tx * 4) = o;
    }
}

// ---------------------------------------------------------------------------
// Kernel 2: flash attention with tf32 mma.sync (FA2-style).
// Block = 128 thr (4 warps), 64 queries per block, 64-key tiles.
// Warp w owns 16 query rows. Q pre-scaled by 1/8, fragments in registers.
// P staged through Ks (K dead after S-phase) to form A-fragments for PV.
// ---------------------------------------------------------------------------
__global__ __launch_bounds__(128) void attn_mma_kernel()
{
    __shared__ float Ks[64][68];   // K tile; later aliased as P tile
    __shared__ float Vs[64][68];   // V tile

    const int tid  = threadIdx.x;
    const int lane = tid & 31;
    const int warp = tid >> 5;
    const int lr   = lane >> 2;    // 0..7
    const int lc   = lane & 3;     // 0..3
    const int wq   = warp * 16;    // warp's query-row base within block
    const int bh   = blockIdx.y;
    const int qt0  = blockIdx.x * 64;

    // ---- stage Q tile (64x64) into Ks, extract A-fragments (scaled, tf32) --
    {
        const float* qg = g_q + ((size_t)bh * TT + qt0) * HS;
        #pragma unroll
        for (int it = 0; it < 8; it++) {
            int idx = tid + it * 128;
            int r = idx >> 4, c4 = idx & 15;
            *(float4*)&Ks[r][c4 * 4] = *(const float4*)(qg + r * 64 + c4 * 4);
        }
    }
    __syncthreads();

    float qa[8][4];
    #pragma unroll
    for (int kk = 0; kk < 8; kk++) {
        qa[kk][0] = to_tf32(Ks[wq + lr    ][kk * 8 + lc    ] * 0.125f);
        qa[kk][1] = to_tf32(Ks[wq + lr + 8][kk * 8 + lc    ] * 0.125f);
        qa[kk][2] = to_tf32(Ks[wq + lr    ][kk * 8 + lc + 4] * 0.125f);
        qa[kk][3] = to_tf32(Ks[wq + lr + 8][kk * 8 + lc + 4] * 0.125f);
    }

    float o[8][4];
    #pragma unroll
    for (int n = 0; n < 8; n++)
        #pragma unroll
        for (int c = 0; c < 4; c++) o[n][c] = 0.f;

    float mlo = -1e30f, mhi = -1e30f;
    float llo = 0.f,    lhi = 0.f;

    const float* kg = g_k + (size_t)bh * TT * HS;
    const float* vg = g_v + (size_t)bh * TT * HS;

    for (int t0 = 0; t0 < TT; t0 += 64) {
        __syncthreads();   // prior tile's P/V reads done before overwrite
        // ---- load K,V tiles (64 keys x 64 dims), tf32-rounded ----
        #pragma unroll
        for (int it = 0; it < 8; it++) {
            int idx = tid + it * 128;
            int r = idx >> 4, c4 = idx & 15;
            float4 kv = *(const float4*)(kg + (size_t)(t0 + r) * 64 + c4 * 4);
            float4 vv = *(const float4*)(vg + (size_t)(t0 + r) * 64 + c4 * 4);
            Ks[r][c4*4+0] = to_tf32(kv.x);
            Ks[r][c4*4+1] = to_tf32(kv.y);
            Ks[r][c4*4+2] = to_tf32(kv.z);
            Ks[r][c4*4+3] = to_tf32(kv.w);
            Vs[r][c4*4+0] = to_tf32(vv.x);
            Vs[r][c4*4+1] = to_tf32(vv.y);
            Vs[r][c4*4+2] = to_tf32(vv.z);
            Vs[r][c4*4+3] = to_tf32(vv.w);
        }
        __syncthreads();

        // ---- S = (Q*scale) K^T : 8 n-tiles x 8 k-steps ----
        float sc[8][4];
        #pragma unroll
        for (int n = 0; n < 8; n++)
            #pragma unroll
            for (int c = 0; c < 4; c++) sc[n][c] = 0.f;

        #pragma unroll
        for (int n = 0; n < 8; n++) {
            #pragma unroll
            for (int kk = 0; kk < 8; kk++) {
                float b0 = Ks[n * 8 + lr][kk * 8 + lc    ];
                float b1 = Ks[n * 8 + lr][kk * 8 + lc + 4];
                mma16n8k8(sc[n], qa[kk], b0, b1);
            }
        }

        // ---- online softmax stats (rows lr, lr+8 of this warp) ----
        float mx_lo = -1e30f, mx_hi = -1e30f;
        #pragma unroll
        for (int n = 0; n < 8; n++) {
            mx_lo = fmaxf(mx_lo, fmaxf(sc[n][0], sc[n][1]));
            mx_hi = fmaxf(mx_hi, fmaxf(sc[n][2], sc[n][3]));
        }
        #pragma unroll
        for (int m = 1; m <= 2; m <<= 1) {
            mx_lo = fmaxf(mx_lo, __shfl_xor_sync(0xffffffffu, mx_lo, m));
            mx_hi = fmaxf(mx_hi, __shfl_xor_sync(0xffffffffu, mx_hi, m));
        }
        float mnlo = fmaxf(mlo, mx_lo);
        float mnhi = fmaxf(mhi, mx_hi);
        float clo = __expf(mlo - mnlo);
        float chi = __expf(mhi - mnhi);
        mlo = mnlo; mhi = mnhi;
        llo *= clo; lhi *= chi;
        #pragma unroll
        for (int n = 0; n < 8; n++) {
            o[n][0] *= clo; o[n][1] *= clo;
            o[n][2] *= chi; o[n][3] *= chi;
        }
        #pragma unroll
        for (int n = 0; n < 8; n++) {
            sc[n][0] = __expf(sc[n][0] - mlo);
            sc[n][1] = __expf(sc[n][1] - mlo);
            sc[n][2] = __expf(sc[n][2] - mhi);
            sc[n][3] = __expf(sc[n][3] - mhi);
            llo += sc[n][0] + sc[n][1];
            lhi += sc[n][2] + sc[n][3];
        }

        __syncthreads();   // all warps finished reading K -> safe to alias as P

        // ---- write P (tf32) into Ks[warp's 16 rows][64 keys] ----
        #pragma unroll
        for (int n = 0; n < 8; n++) {
            float2 plo = make_float2(to_tf32(sc[n][0]), to_tf32(sc[n][1]));
            float2 phi = make_float2(to_tf32(sc[n][2]), to_tf32(sc[n][3]));
            *(float2*)&Ks[wq + lr    ][n * 8 + 2 * lc] = plo;
            *(float2*)&Ks[wq + lr + 8][n * 8 + 2 * lc] = phi;
        }
        __syncwarp();

        // ---- O += P V : 8 k-steps (keys) x 8 n-tiles (dims) ----
        #pragma unroll
        for (int kk = 0; kk < 8; kk++) {
            float pa[4];
            pa[0] = Ks[wq + lr    ][kk * 8 + lc    ];
            pa[1] = Ks[wq + lr + 8][kk * 8 + lc    ];
            pa[2] = Ks[wq + lr    ][kk * 8 + lc + 4];
            pa[3] = Ks[wq + lr + 8][kk * 8 + lc + 4];
            #pragma unroll
            for (int n = 0; n < 8; n++) {
                float b0 = Vs[kk * 8 + lc    ][n * 8 + lr];
                float b1 = Vs[kk * 8 + lc + 4][n * 8 + lr];
                mma16n8k8(o[n], pa, b0, b1);
            }
        }
    }

    // ---- finalize: reduce l across quad, normalize, write out ----
    #pragma unroll
    for (int m = 1; m <= 2; m <<= 1) {
        llo += __shfl_xor_sync(0xffffffffu, llo, m);
        lhi += __shfl_xor_sync(0xffffffffu, lhi, m);
    }
    float inv_lo = 1.f / llo;
    float inv_hi = 1.f / lhi;

    const int bb = bh / HH;
    const int hh = bh % HH;
    const int row_lo = qt0 + wq + lr;
    float* og_lo = g_attn + ((size_t)bb * TT + row_lo    ) * DD + hh * HS;
    float* og_hi = g_attn + ((size_t)bb * TT + row_lo + 8) * DD + hh * HS;
    #pragma unroll
    for (int n = 0; n < 8; n++) {
        *(float2*)(og_lo + n * 8 + 2 * lc) =
            make_float2(o[n][0] * inv_lo, o[n][1] * inv_lo);
        *(float2*)(og_hi + n * 8 + 2 * lc) =
            make_float2(o[n][2] * inv_hi, o[n][3] * inv_hi);
    }
}

// ---------------------------------------------------------------------------
// Kernel 3: output projection (unchanged from R0 baseline).
// ---------------------------------------------------------------------------
__global__ __launch_bounds__(256) void oproj_kernel(
    const float* __restrict__ Wo,
    const float* __restrict__ bo,
    float* __restrict__ out)
{
    __shared__ float xs[BK][XS_LD];
    __shared__ float ws[BK][64];

    const int tid = threadIdx.x;
    const int tx = tid & 15;
    const int ty = tid >> 4;
    const int m0 = blockIdx.x * 64;
    const int n0 = blockIdx.y * 64;

    float acc[4][4];
    #pragma unroll
    for (int i = 0; i < 4; i++)
        #pragma unroll
        for (int j = 0; j < 4; j++) acc[i][j] = 0.f;

    for (int k0 = 0; k0 < DD; k0 += BK) {
        __syncthreads();
        #pragma unroll
        for (int it = 0; it < 2; it++) {
            int idx = tid + it * 256;
            int r = idx >> 3, c4 = idx & 7;
            float4 v = *(const float4*)(g_attn + (size_t)(m0 + r) * DD + k0 + c4 * 4);
            xs[c4*4+0][r] = v.x;
            xs[c4*4+1][r] = v.y;
            xs[c4*4+2][r] = v.z;
            xs[c4*4+3][r] = v.w;
        }
        #pragma unroll
        for (int it = 0; it < 2; it++) {
            int idx = tid + it * 256;
            int kk = idx >> 4, e4 = idx & 15;
            *(float4*)&ws[kk][e4*4] =
                *(const float4*)(Wo + (size_t)(k0 + kk) * DD + n0 + e4 * 4);
        }
        __syncthreads();
        #pragma unroll
        for (int kk = 0; kk < BK; kk++) {
            float4 a4 = *(const float4*)&xs[kk][ty*4];
            float4 b4 = *(const float4*)&ws[kk][tx*4];
            float av[4] = {a4.x, a4.y, a4.z, a4.w};
            float bv[4] = {b4.x, b4.y, b4.z, b4.w};
            #pragma unroll
            for (int i = 0; i < 4; i++)
                #pragma unroll
                for (int j = 0; j < 4; j++)
                    acc[i][j] += av[i] * bv[j];
        }
    }

    float4 bias = *(const float4*)(bo + n0 + tx * 4);
    #pragma unroll
    for (int i = 0; i < 4; i++) {
        int m = m0 + ty * 4 + i;
        float4 o = make_float4(acc[i][0] + bias.x, acc[i][1] + bias.y,
                               acc[i][2] + bias.z, acc[i][3] + bias.w);
        *(float4*)(out + (size_t)m * DD + n0 + tx * 4) = o;
    }
}

// ---------------------------------------------------------------------------
extern "C" void kernel_launch(void* const* d_in, const int* in_sizes, int n_in,
                              void* d_out, int out_size)
{
    const float* x  = (const float*)d_in[0];
    const float* Wq = (const float*)d_in[1];
    const float* Wk = (const float*)d_in[2];
    const float* Wv = (const float*)d_in[3];
    const float* Wo = (const float*)d_in[4];
    const float* bo = (const float*)d_in[5];
    float* out = (float*)d_out;

    dim3 g1((BB * TT) / 64, HH, 3);
    qkv_proj_kernel<<<g1, 256>>>(x, Wq, Wk, Wv);

    dim3 g2(TT / 64, BB * HH);
    attn_mma_kernel<<<g2, 128>>>();

    dim3 g3((BB * TT) / 64, DD / 64);
    oproj_kernel<<<g3, 256>>>(Wo, bo, out);
}

// round 4
// speedup vs baseline: 3.6884x; 1.6129x over previous
#include <cuda_runtime.h>
#include <cstdint>

#define BB 4
#define TT 2048
#define DD 512
#define HH 8
#define HS 64

// Scratch (allocation-free rule: __device__ globals)
__device__ float g_q[BB*HH*TT*HS];     // [B,H,T,HS]
__device__ float g_k[BB*HH*TT*HS];
__device__ float g_v[BB*HH*TT*HS];
__device__ float g_attn[BB*TT*DD];     // [B,T,D] (heads concatenated)

// ---------------------------------------------------------------------------
// helpers
// ---------------------------------------------------------------------------
__device__ __forceinline__ float to_tf32(float x) {
    uint32_t u;
    asm("cvt.rna.tf32.f32 %0, %1;" : "=r"(u) : "f"(x));
    return __uint_as_float(u);
}

__device__ __forceinline__ void mma16n8k8(float c[4], const float a[4],
                                          float b0, float b1) {
    asm volatile(
        "mma.sync.aligned.m16n8k8.row.col.f32.tf32.tf32.f32 "
        "{%0,%1,%2,%3}, {%4,%5,%6,%7}, {%8,%9}, {%0,%1,%2,%3};"
        : "+f"(c[0]), "+f"(c[1]), "+f"(c[2]), "+f"(c[3])
        : "r"(__float_as_uint(a[0])), "r"(__float_as_uint(a[1])),
          "r"(__float_as_uint(a[2])), "r"(__float_as_uint(a[3])),
          "r"(__float_as_uint(b0)),  "r"(__float_as_uint(b1)));
}

// ---------------------------------------------------------------------------
// Kernel 1: QKV projections, tf32 mma.
// grid (BT/128=64, H=8, 3), block 128 (4 warps).
// Warp: 32 rows (2 m-tiles) x 64 cols, K chunked by 32.
// ---------------------------------------------------------------------------
__global__ __launch_bounds__(128) void qkv_mma_kernel(
    const float* __restrict__ x,
    const float* __restrict__ Wq,
    const float* __restrict__ Wk,
    const float* __restrict__ Wv)
{
    __shared__ float xs[128][36];   // 128 rows x 32 (k) + pad
    __shared__ float ws[32][68];    // 32 (k) x 64 (n) + pad

    const int tid  = threadIdx.x;
    const int lane = tid & 31;
    const int warp = tid >> 5;
    const int lr   = lane >> 2;
    const int lc   = lane & 3;
    const int m0   = blockIdx.x * 128;
    const int h    = blockIdx.y;
    const int wsel = blockIdx.z;

    const float* W = (wsel == 0) ? Wq : (wsel == 1 ? Wk : Wv);
    W += (size_t)h * DD * HS;
    float* out = (wsel == 0) ? g_q : (wsel == 1 ? g_k : g_v);

    float acc[2][8][4];
    #pragma unroll
    for (int mi = 0; mi < 2; mi++)
        #pragma unroll
        for (int n = 0; n < 8; n++)
            #pragma unroll
            for (int c = 0; c < 4; c++) acc[mi][n][c] = 0.f;

    for (int k0 = 0; k0 < DD; k0 += 32) {
        __syncthreads();
        // x tile: 128 rows x 32 floats = 1024 float4 -> 8 per thread
        #pragma unroll
        for (int it = 0; it < 8; it++) {
            int idx = tid + it * 128;
            int r = idx >> 3, c4 = idx & 7;
            float4 v = *(const float4*)(x + (size_t)(m0 + r) * DD + k0 + c4 * 4);
            xs[r][c4*4+0] = to_tf32(v.x);
            xs[r][c4*4+1] = to_tf32(v.y);
            xs[r][c4*4+2] = to_tf32(v.z);
            xs[r][c4*4+3] = to_tf32(v.w);
        }
        // W tile: 32 rows x 64 floats = 512 float4 -> 4 per thread
        #pragma unroll
        for (int it = 0; it < 4; it++) {
            int idx = tid + it * 128;
            int kk = idx >> 4, e4 = idx & 15;
            float4 w = *(const float4*)(W + (size_t)(k0 + kk) * HS + e4 * 4);
            ws[kk][e4*4+0] = to_tf32(w.x);
            ws[kk][e4*4+1] = to_tf32(w.y);
            ws[kk][e4*4+2] = to_tf32(w.z);
            ws[kk][e4*4+3] = to_tf32(w.w);
        }
        __syncthreads();

        #pragma unroll
        for (int kk = 0; kk < 4; kk++) {
            float a[2][4];
            #pragma unroll
            for (int mi = 0; mi < 2; mi++) {
                int row = warp * 32 + mi * 16;
                a[mi][0] = xs[row + lr    ][kk * 8 + lc    ];
                a[mi][1] = xs[row + lr + 8][kk * 8 + lc    ];
                a[mi][2] = xs[row + lr    ][kk * 8 + lc + 4];
                a[mi][3] = xs[row + lr + 8][kk * 8 + lc + 4];
            }
            #pragma unroll
            for (int n = 0; n < 8; n++) {
                float b0 = ws[kk * 8 + lc    ][n * 8 + lr];
                float b1 = ws[kk * 8 + lc + 4][n * 8 + lr];
                mma16n8k8(acc[0][n], a[0], b0, b1);
                mma16n8k8(acc[1][n], a[1], b0, b1);
            }
        }
    }

    // write out: rows m0 + warp*32 + mi*16 + lr (+8), cols n*8 + 2*lc (+1)
    #pragma unroll
    for (int mi = 0; mi < 2; mi++) {
        #pragma unroll
        for (int half = 0; half < 2; half++) {
            int m = m0 + warp * 32 + mi * 16 + lr + half * 8;
            int bb = m >> 11;
            int t  = m & (TT - 1);
            float* og = out + ((size_t)(bb * HH + h) * TT + t) * HS;
            #pragma unroll
            for (int n = 0; n < 8; n++) {
                *(float2*)(og + n * 8 + 2 * lc) =
                    make_float2(acc[mi][n][half * 2], acc[mi][n][half * 2 + 1]);
            }
        }
    }
}

// ---------------------------------------------------------------------------
// Kernel 2: flash attention with tf32 mma.sync (unchanged from R2).
// ---------------------------------------------------------------------------
__global__ __launch_bounds__(128) void attn_mma_kernel()
{
    __shared__ float Ks[64][68];
    __shared__ float Vs[64][68];

    const int tid  = threadIdx.x;
    const int lane = tid & 31;
    const int warp = tid >> 5;
    const int lr   = lane >> 2;
    const int lc   = lane & 3;
    const int wq   = warp * 16;
    const int bh   = blockIdx.y;
    const int qt0  = blockIdx.x * 64;

    {
        const float* qg = g_q + ((size_t)bh * TT + qt0) * HS;
        #pragma unroll
        for (int it = 0; it < 8; it++) {
            int idx = tid + it * 128;
            int r = idx >> 4, c4 = idx & 15;
            *(float4*)&Ks[r][c4 * 4] = *(const float4*)(qg + r * 64 + c4 * 4);
        }
    }
    __syncthreads();

    float qa[8][4];
    #pragma unroll
    for (int kk = 0; kk < 8; kk++) {
        qa[kk][0] = to_tf32(Ks[wq + lr    ][kk * 8 + lc    ] * 0.125f);
        qa[kk][1] = to_tf32(Ks[wq + lr + 8][kk * 8 + lc    ] * 0.125f);
        qa[kk][2] = to_tf32(Ks[wq + lr    ][kk * 8 + lc + 4] * 0.125f);
        qa[kk][3] = to_tf32(Ks[wq + lr + 8][kk * 8 + lc + 4] * 0.125f);
    }

    float o[8][4];
    #pragma unroll
    for (int n = 0; n < 8; n++)
        #pragma unroll
        for (int c = 0; c < 4; c++) o[n][c] = 0.f;

    float mlo = -1e30f, mhi = -1e30f;
    float llo = 0.f,    lhi = 0.f;

    const float* kg = g_k + (size_t)bh * TT * HS;
    const float* vg = g_v + (size_t)bh * TT * HS;

    for (int t0 = 0; t0 < TT; t0 += 64) {
        __syncthreads();
        #pragma unroll
        for (int it = 0; it < 8; it++) {
            int idx = tid + it * 128;
            int r = idx >> 4, c4 = idx & 15;
            float4 kv = *(const float4*)(kg + (size_t)(t0 + r) * 64 + c4 * 4);
            float4 vv = *(const float4*)(vg + (size_t)(t0 + r) * 64 + c4 * 4);
            Ks[r][c4*4+0] = to_tf32(kv.x);
            Ks[r][c4*4+1] = to_tf32(kv.y);
            Ks[r][c4*4+2] = to_tf32(kv.z);
            Ks[r][c4*4+3] = to_tf32(kv.w);
            Vs[r][c4*4+0] = to_tf32(vv.x);
            Vs[r][c4*4+1] = to_tf32(vv.y);
            Vs[r][c4*4+2] = to_tf32(vv.z);
            Vs[r][c4*4+3] = to_tf32(vv.w);
        }
        __syncthreads();

        float sc[8][4];
        #pragma unroll
        for (int n = 0; n < 8; n++)
            #pragma unroll
            for (int c = 0; c < 4; c++) sc[n][c] = 0.f;

        #pragma unroll
        for (int n = 0; n < 8; n++) {
            #pragma unroll
            for (int kk = 0; kk < 8; kk++) {
                float b0 = Ks[n * 8 + lr][kk * 8 + lc    ];
                float b1 = Ks[n * 8 + lr][kk * 8 + lc + 4];
                mma16n8k8(sc[n], qa[kk], b0, b1);
            }
        }

        float mx_lo = -1e30f, mx_hi = -1e30f;
        #pragma unroll
        for (int n = 0; n < 8; n++) {
            mx_lo = fmaxf(mx_lo, fmaxf(sc[n][0], sc[n][1]));
            mx_hi = fmaxf(mx_hi, fmaxf(sc[n][2], sc[n][3]));
        }
        #pragma unroll
        for (int m = 1; m <= 2; m <<= 1) {
            mx_lo = fmaxf(mx_lo, __shfl_xor_sync(0xffffffffu, mx_lo, m));
            mx_hi = fmaxf(mx_hi, __shfl_xor_sync(0xffffffffu, mx_hi, m));
        }
        float mnlo = fmaxf(mlo, mx_lo);
        float mnhi = fmaxf(mhi, mx_hi);
        float clo = __expf(mlo - mnlo);
        float chi = __expf(mhi - mnhi);
        mlo = mnlo; mhi = mnhi;
        llo *= clo; lhi *= chi;
        #pragma unroll
        for (int n = 0; n < 8; n++) {
            o[n][0] *= clo; o[n][1] *= clo;
            o[n][2] *= chi; o[n][3] *= chi;
        }
        #pragma unroll
        for (int n = 0; n < 8; n++) {
            sc[n][0] = __expf(sc[n][0] - mlo);
            sc[n][1] = __expf(sc[n][1] - mlo);
            sc[n][2] = __expf(sc[n][2] - mhi);
            sc[n][3] = __expf(sc[n][3] - mhi);
            llo += sc[n][0] + sc[n][1];
            lhi += sc[n][2] + sc[n][3];
        }

        __syncthreads();

        #pragma unroll
        for (int n = 0; n < 8; n++) {
            float2 plo = make_float2(to_tf32(sc[n][0]), to_tf32(sc[n][1]));
            float2 phi = make_float2(to_tf32(sc[n][2]), to_tf32(sc[n][3]));
            *(float2*)&Ks[wq + lr    ][n * 8 + 2 * lc] = plo;
            *(float2*)&Ks[wq + lr + 8][n * 8 + 2 * lc] = phi;
        }
        __syncwarp();

        #pragma unroll
        for (int kk = 0; kk < 8; kk++) {
            float pa[4];
            pa[0] = Ks[wq + lr    ][kk * 8 + lc    ];
            pa[1] = Ks[wq + lr + 8][kk * 8 + lc    ];
            pa[2] = Ks[wq + lr    ][kk * 8 + lc + 4];
            pa[3] = Ks[wq + lr + 8][kk * 8 + lc + 4];
            #pragma unroll
            for (int n = 0; n < 8; n++) {
                float b0 = Vs[kk * 8 + lc    ][n * 8 + lr];
                float b1 = Vs[kk * 8 + lc + 4][n * 8 + lr];
                mma16n8k8(o[n], pa, b0, b1);
            }
        }
    }

    #pragma unroll
    for (int m = 1; m <= 2; m <<= 1) {
        llo += __shfl_xor_sync(0xffffffffu, llo, m);
        lhi += __shfl_xor_sync(0xffffffffu, lhi, m);
    }
    float inv_lo = 1.f / llo;
    float inv_hi = 1.f / lhi;

    const int bb = bh / HH;
    const int hh = bh % HH;
    const int row_lo = qt0 + wq + lr;
    float* og_lo = g_attn + ((size_t)bb * TT + row_lo    ) * DD + hh * HS;
    float* og_hi = g_attn + ((size_t)bb * TT + row_lo + 8) * DD + hh * HS;
    #pragma unroll
    for (int n = 0; n < 8; n++) {
        *(float2*)(og_lo + n * 8 + 2 * lc) =
            make_float2(o[n][0] * inv_lo, o[n][1] * inv_lo);
        *(float2*)(og_hi + n * 8 + 2 * lc) =
            make_float2(o[n][2] * inv_hi, o[n][3] * inv_hi);
    }
}

// ---------------------------------------------------------------------------
// Kernel 3: output projection, tf32 mma.
// grid (BT/128=64, D/64=8), block 128 (4 warps). Warp: 32 rows x 64 cols.
// ---------------------------------------------------------------------------
__global__ __launch_bounds__(128) void oproj_mma_kernel(
    const float* __restrict__ Wo,
    const float* __restrict__ bo,
    float* __restrict__ out)
{
    __shared__ float xs[128][36];
    __shared__ float ws[32][68];

    const int tid  = threadIdx.x;
    const int lane = tid & 31;
    const int warp = tid >> 5;
    const int lr   = lane >> 2;
    const int lc   = lane & 3;
    const int m0   = blockIdx.x * 128;
    const int n0   = blockIdx.y * 64;

    float acc[2][8][4];
    #pragma unroll
    for (int mi = 0; mi < 2; mi++)
        #pragma unroll
        for (int n = 0; n < 8; n++)
            #pragma unroll
            for (int c = 0; c < 4; c++) acc[mi][n][c] = 0.f;

    for (int k0 = 0; k0 < DD; k0 += 32) {
        __syncthreads();
        #pragma unroll
        for (int it = 0; it < 8; it++) {
            int idx = tid + it * 128;
            int r = idx >> 3, c4 = idx & 7;
            float4 v = *(const float4*)(g_attn + (size_t)(m0 + r) * DD + k0 + c4 * 4);
            xs[r][c4*4+0] = to_tf32(v.x);
            xs[r][c4*4+1] = to_tf32(v.y);
            xs[r][c4*4+2] = to_tf32(v.z);
            xs[r][c4*4+3] = to_tf32(v.w);
        }
        #pragma unroll
        for (int it = 0; it < 4; it++) {
            int idx = tid + it * 128;
            int kk = idx >> 4, e4 = idx & 15;
            float4 w = *(const float4*)(Wo + (size_t)(k0 + kk) * DD + n0 + e4 * 4);
            ws[kk][e4*4+0] = to_tf32(w.x);
            ws[kk][e4*4+1] = to_tf32(w.y);
            ws[kk][e4*4+2] = to_tf32(w.z);
            ws[kk][e4*4+3] = to_tf32(w.w);
        }
        __syncthreads();

        #pragma unroll
        for (int kk = 0; kk < 4; kk++) {
            float a[2][4];
            #pragma unroll
            for (int mi = 0; mi < 2; mi++) {
                int row = warp * 32 + mi * 16;
                a[mi][0] = xs[row + lr    ][kk * 8 + lc    ];
                a[mi][1] = xs[row + lr + 8][kk * 8 + lc    ];
                a[mi][2] = xs[row + lr    ][kk * 8 + lc + 4];
                a[mi][3] = xs[row + lr + 8][kk * 8 + lc + 4];
            }
            #pragma unroll
            for (int n = 0; n < 8; n++) {
                float b0 = ws[kk * 8 + lc    ][n * 8 + lr];
                float b1 = ws[kk * 8 + lc + 4][n * 8 + lr];
                mma16n8k8(acc[0][n], a[0], b0, b1);
                mma16n8k8(acc[1][n], a[1], b0, b1);
            }
        }
    }

    #pragma unroll
    for (int mi = 0; mi < 2; mi++) {
        #pragma unroll
        for (int half = 0; half < 2; half++) {
            int m = m0 + warp * 32 + mi * 16 + lr + half * 8;
            float* og = out + (size_t)m * DD + n0;
            #pragma unroll
            for (int n = 0; n < 8; n++) {
                float2 bias = *(const float2*)(bo + n0 + n * 8 + 2 * lc);
                *(float2*)(og + n * 8 + 2 * lc) =
                    make_float2(acc[mi][n][half * 2]     + bias.x,
                                acc[mi][n][half * 2 + 1] + bias.y);
            }
        }
    }
}

// ---------------------------------------------------------------------------
extern "C" void kernel_launch(void* const* d_in, const int* in_sizes, int n_in,
                              void* d_out, int out_size)
{
    const float* x  = (const float*)d_in[0];
    const float* Wq = (const float*)d_in[1];
    const float* Wk = (const float*)d_in[2];
    const float* Wv = (const float*)d_in[3];
    const float* Wo = (const float*)d_in[4];
    const float* bo = (const float*)d_in[5];
    float* out = (float*)d_out;

    dim3 g1((BB * TT) / 128, HH, 3);
    qkv_mma_kernel<<<g1, 128>>>(x, Wq, Wk, Wv);

    dim3 g2(TT / 64, BB * HH);
    attn_mma_kernel<<<g2, 128>>>();

    dim3 g3((BB * TT) / 128, DD / 64);
    oproj_mma_kernel<<<g3, 128>>>(Wo, bo, out);
}

// round 5
// speedup vs baseline: 4.1961x; 1.1377x over previous
#include <cuda_runtime.h>
#include <cstdint>

#define BB 4
#define TT 2048
#define DD 512
#define HH 8
#define HS 64

// Pre-rounded (tf32) copies + intermediates (all __device__ globals: alloc-free)
__device__ float g_xr[BB*TT*DD];
__device__ float g_wq[HH*DD*HS];
__device__ float g_wk[HH*DD*HS];
__device__ float g_wv[HH*DD*HS];
__device__ float g_wo[DD*DD];
__device__ float g_q[BB*HH*TT*HS];     // [B,H,T,HS] (tf32 values)
__device__ float g_k[BB*HH*TT*HS];
__device__ float g_v[BB*HH*TT*HS];
__device__ float g_attn[BB*TT*DD];     // [B,T,D]    (tf32 values)

// ---------------------------------------------------------------------------
// helpers
// ---------------------------------------------------------------------------
__device__ __forceinline__ float to_tf32(float x) {
    uint32_t u;
    asm("cvt.rna.tf32.f32 %0, %1;" : "=r"(u) : "f"(x));
    return __uint_as_float(u);
}

__device__ __forceinline__ void mma16n8k8(float c[4], const float a[4],
                                          float b0, float b1) {
    asm volatile(
        "mma.sync.aligned.m16n8k8.row.col.f32.tf32.tf32.f32 "
        "{%0,%1,%2,%3}, {%4,%5,%6,%7}, {%8,%9}, {%0,%1,%2,%3};"
        : "+f"(c[0]), "+f"(c[1]), "+f"(c[2]), "+f"(c[3])
        : "r"(__float_as_uint(a[0])), "r"(__float_as_uint(a[1])),
          "r"(__float_as_uint(a[2])), "r"(__float_as_uint(a[3])),
          "r"(__float_as_uint(b0)),  "r"(__float_as_uint(b1)));
}

__device__ __forceinline__ void cpa16(uint32_t dst, const void* src) {
    asm volatile("cp.async.ca.shared.global [%0], [%1], 16;" :: "r"(dst), "l"(src));
}
__device__ __forceinline__ void cpa_commit() {
    asm volatile("cp.async.commit_group;");
}
__device__ __forceinline__ void cpa_wait0() {
    asm volatile("cp.async.wait_group 0;");
}
__device__ __forceinline__ void cpa_wait1() {
    asm volatile("cp.async.wait_group 1;");
}

// ---------------------------------------------------------------------------
// Prep: round inputs to tf32 once (RNA). to_tf32 is idempotent -> numerics
// identical to converting at use-sites, but mainloops lose all cvts and can
// use cp.async.
// ---------------------------------------------------------------------------
__global__ __launch_bounds__(256) void round_x_kernel(const float* __restrict__ x) {
    int i = blockIdx.x * 256 + threadIdx.x;            // float4 index
    float4 v = ((const float4*)x)[i];
    v.x = to_tf32(v.x); v.y = to_tf32(v.y); v.z = to_tf32(v.z); v.w = to_tf32(v.w);
    ((float4*)g_xr)[i] = v;
}

__global__ __launch_bounds__(256) void round_w_kernel(
    const float* __restrict__ Wq, const float* __restrict__ Wk,
    const float* __restrict__ Wv, const float* __restrict__ Wo) {
    int i = blockIdx.x * 256 + threadIdx.x;            // float4 index, 65536 per tensor
    int sel = blockIdx.y;
    const float* src = (sel == 0) ? Wq : (sel == 1) ? Wk : (sel == 2) ? Wv : Wo;
    float* dst = (sel == 0) ? g_wq : (sel == 1) ? g_wk : (sel == 2) ? g_wv : g_wo;
    float4 v = ((const float4*)src)[i];
    v.x = to_tf32(v.x); v.y = to_tf32(v.y); v.z = to_tf32(v.z); v.w = to_tf32(v.w);
    ((float4*)dst)[i] = v;
}

// ---------------------------------------------------------------------------
// Kernel 1: QKV projections, tf32 mma + cp.async double buffer.
// grid (BT/128=64, H=8, 3), block 128 (4 warps). Warp: 32 rows x 64 cols.
// dyn smem: xs[2][128][36] + ws[2][32][68] = 54272 B
// ---------------------------------------------------------------------------
#define XS_STR 36
#define WS_STR 68
#define XS_BUF (128 * XS_STR)
#define WS_BUF (32 * WS_STR)

__global__ __launch_bounds__(128, 4) void qkv_mma_kernel()
{
    extern __shared__ float sm[];
    float* xs = sm;                     // [2][128][36]
    float* ws = sm + 2 * XS_BUF;        // [2][32][68]

    const int tid  = threadIdx.x;
    const int lane = tid & 31;
    const int warp = tid >> 5;
    const int lr   = lane >> 2;
    const int lc   = lane & 3;
    const int m0   = blockIdx.x * 128;
    const int h    = blockIdx.y;
    const int wsel = blockIdx.z;

    const float* X = g_xr;
    const float* W = ((wsel == 0) ? g_wq : (wsel == 1) ? g_wk : g_wv)
                     + (size_t)h * DD * HS;
    float* out = (wsel == 0) ? g_q : (wsel == 1) ? g_k : g_v;

    const uint32_t xs_s = (uint32_t)__cvta_generic_to_shared(xs);
    const uint32_t ws_s = (uint32_t)__cvta_generic_to_shared(ws);

    // per-thread cp.async slots
    const int xr = tid >> 3, xc4 = tid & 7;      // x: 8 iters of (r += 16)
    const int wk = tid >> 4, we4 = tid & 15;     // w: 4 iters of (k += 8)

    #define QKV_ISSUE(chunk, buf) do {                                          \
        int k0_ = (chunk) * 32;                                                 \
        _Pragma("unroll")                                                       \
        for (int it = 0; it < 8; it++) {                                        \
            int r = xr + it * 16;                                               \
            cpa16(xs_s + ((buf) * XS_BUF + r * XS_STR + xc4 * 4) * 4,           \
                  X + (size_t)(m0 + r) * DD + k0_ + xc4 * 4);                   \
        }                                                                       \
        _Pragma("unroll")                                                       \
        for (int it = 0; it < 4; it++) {                                        \
            int kk = wk + it * 8;                                               \
            cpa16(ws_s + ((buf) * WS_BUF + kk * WS_STR + we4 * 4) * 4,          \
                  W + (size_t)(k0_ + kk) * HS + we4 * 4);                       \
        }                                                                       \
    } while (0)

    float acc[2][8][4];
    #pragma unroll
    for (int mi = 0; mi < 2; mi++)
        #pragma unroll
        for (int n = 0; n < 8; n++)
            #pragma unroll
            for (int c = 0; c < 4; c++) acc[mi][n][c] = 0.f;

    QKV_ISSUE(0, 0);
    cpa_commit();

    for (int c = 0; c < 16; c++) {
        int cur = c & 1;
        if (c < 15) { QKV_ISSUE(c + 1, cur ^ 1); cpa_commit(); cpa_wait1(); }
        else        { cpa_wait0(); }
        __syncthreads();

        const float* xb = xs + cur * XS_BUF;
        const float* wb = ws + cur * WS_BUF;
        #pragma unroll
        for (int kk = 0; kk < 4; kk++) {
            float a[2][4];
            #pragma unroll
            for (int mi = 0; mi < 2; mi++) {
                int row = warp * 32 + mi * 16;
                a[mi][0] = xb[(row + lr    ) * XS_STR + kk * 8 + lc    ];
                a[mi][1] = xb[(row + lr + 8) * XS_STR + kk * 8 + lc    ];
                a[mi][2] = xb[(row + lr    ) * XS_STR + kk * 8 + lc + 4];
                a[mi][3] = xb[(row + lr + 8) * XS_STR + kk * 8 + lc + 4];
            }
            #pragma unroll
            for (int n = 0; n < 8; n++) {
                float b0 = wb[(kk * 8 + lc    ) * WS_STR + n * 8 + lr];
                float b1 = wb[(kk * 8 + lc + 4) * WS_STR + n * 8 + lr];
                mma16n8k8(acc[0][n], a[0], b0, b1);
                mma16n8k8(acc[1][n], a[1], b0, b1);
            }
        }
        __syncthreads();
    }

    // epilogue: write tf32-rounded (so attention consumes without cvt)
    #pragma unroll
    for (int mi = 0; mi < 2; mi++) {
        #pragma unroll
        for (int half = 0; half < 2; half++) {
            int m = m0 + warp * 32 + mi * 16 + lr + half * 8;
            int bb = m >> 11;
            int t  = m & (TT - 1);
            float* og = out + ((size_t)(bb * HH + h) * TT + t) * HS;
            #pragma unroll
            for (int n = 0; n < 8; n++) {
                *(float2*)(og + n * 8 + 2 * lc) =
                    make_float2(to_tf32(acc[mi][n][half * 2]),
                                to_tf32(acc[mi][n][half * 2 + 1]));
            }
        }
    }
}

// ---------------------------------------------------------------------------
// Kernel 2: flash attention, tf32 mma, 128 q/block, 2 m-tiles/warp,
// cp.async double-buffered K/V, P via register shuffle (no smem round trip).
// dyn smem: Qs[128][68] + Ks[2][64][68] + Vs[2][64][68] = 104448 B
// ---------------------------------------------------------------------------
#define AS_STR 68
#define Q_BUF  (128 * AS_STR)
#define KV_BUF (64 * AS_STR)

__global__ __launch_bounds__(128, 2) void attn_mma_kernel()
{
    extern __shared__ float sm[];
    float* Qs = sm;                       // [128][68]
    float* Ks = sm + Q_BUF;               // [2][64][68]
    float* Vs = sm + Q_BUF + 2 * KV_BUF;  // [2][64][68]

    const int tid  = threadIdx.x;
    const int lane = tid & 31;
    const int warp = tid >> 5;
    const int lr   = lane >> 2;
    const int lc   = lane & 3;
    const int bh   = blockIdx.y;
    const int qt0  = blockIdx.x * 128;
    const int src  = (lane & 28) | (lc >> 1);   // quad shfl source (j = lc)
    const int src2 = src + 2;                   // (j = lc + 4)

    const float* qg = g_q + ((size_t)bh * TT + qt0) * HS;
    const float* kg = g_k + (size_t)bh * TT * HS;
    const float* vg = g_v + (size_t)bh * TT * HS;

    const uint32_t qs_s = (uint32_t)__cvta_generic_to_shared(Qs);
    const uint32_t ks_s = (uint32_t)__cvta_generic_to_shared(Ks);
    const uint32_t vs_s = (uint32_t)__cvta_generic_to_shared(Vs);

    const int kvr = tid >> 4, kvc4 = tid & 15;  // 64x16 float4 slots, r += 8 x4

    #define ATTN_ISSUE_KV(tile, buf) do {                                       \
        int t0_ = (tile) * 64;                                                  \
        _Pragma("unroll")                                                       \
        for (int it = 0; it < 8; it++) {                                        \
            int r = kvr + it * 8;                                               \
            uint32_t off = ((buf) * KV_BUF + r * AS_STR + kvc4 * 4) * 4;        \
            const float* gsrc = kg + (size_t)(t0_ + r) * HS + kvc4 * 4;         \
            cpa16(ks_s + off, gsrc);                                            \
            cpa16(vs_s + off, vg + (size_t)(t0_ + r) * HS + kvc4 * 4);          \
        }                                                                       \
    } while (0)

    // prologue: Q + KV tile 0
    {
        const int qr = tid >> 4, qc4 = tid & 15;
        #pragma unroll
        for (int it = 0; it < 16; it++) {
            int r = qr + it * 8;
            cpa16(qs_s + (r * AS_STR + qc4 * 4) * 4, qg + (size_t)r * HS + qc4 * 4);
        }
        ATTN_ISSUE_KV(0, 0);
        cpa_commit();
        cpa_wait0();
        __syncthreads();
    }

    // Q fragments, pre-scaled by 1/8 (exact exponent shift on tf32 values)
    float qa[2][8][4];
    #pragma unroll
    for (int mi = 0; mi < 2; mi++) {
        int row = warp * 32 + mi * 16;
        #pragma unroll
        for (int kk = 0; kk < 8; kk++) {
            qa[mi][kk][0] = Qs[(row + lr    ) * AS_STR + kk * 8 + lc    ] * 0.125f;
            qa[mi][kk][1] = Qs[(row + lr + 8) * AS_STR + kk * 8 + lc    ] * 0.125f;
            qa[mi][kk][2] = Qs[(row + lr    ) * AS_STR + kk * 8 + lc + 4] * 0.125f;
            qa[mi][kk][3] = Qs[(row + lr + 8) * AS_STR + kk * 8 + lc + 4] * 0.125f;
        }
    }

    float o[2][8][4];
    float mm[2][2], ll[2][2];
    #pragma unroll
    for (int mi = 0; mi < 2; mi++) {
        #pragma unroll
        for (int n = 0; n < 8; n++)
            #pragma unroll
            for (int c = 0; c < 4; c++) o[mi][n][c] = 0.f;
        mm[mi][0] = mm[mi][1] = -1e30f;
        ll[mi][0] = ll[mi][1] = 0.f;
    }

    for (int t = 0; t < TT / 64; t++) {
        int cur = t & 1;
        if (t < TT / 64 - 1) { ATTN_ISSUE_KV(t + 1, cur ^ 1); cpa_commit(); cpa_wait1(); }
        else                 { cpa_wait0(); }
        __syncthreads();

        const float* kb = Ks + cur * KV_BUF;
        const float* vb = Vs + cur * KV_BUF;

        // ---- S = Q K^T ----
        float sc[2][8][4];
        #pragma unroll
        for (int mi = 0; mi < 2; mi++)
            #pragma unroll
            for (int n = 0; n < 8; n++)
                #pragma unroll
                for (int c = 0; c < 4; c++) sc[mi][n][c] = 0.f;

        #pragma unroll
        for (int kk = 0; kk < 8; kk++) {
            #pragma unroll
            for (int n = 0; n < 8; n++) {
                float b0 = kb[(n * 8 + lr) * AS_STR + kk * 8 + lc    ];
                float b1 = kb[(n * 8 + lr) * AS_STR + kk * 8 + lc + 4];
                mma16n8k8(sc[0][n], qa[0][kk], b0, b1);
                mma16n8k8(sc[1][n], qa[1][kk], b0, b1);
            }
        }

        // ---- online softmax per m-tile ----
        #pragma unroll
        for (int mi = 0; mi < 2; mi++) {
            float mx0 = -1e30f, mx1 = -1e30f;
            #pragma unroll
            for (int n = 0; n < 8; n++) {
                mx0 = fmaxf(mx0, fmaxf(sc[mi][n][0], sc[mi][n][1]));
                mx1 = fmaxf(mx1, fmaxf(sc[mi][n][2], sc[mi][n][3]));
            }
            #pragma unroll
            for (int m = 1; m <= 2; m <<= 1) {
                mx0 = fmaxf(mx0, __shfl_xor_sync(0xffffffffu, mx0, m));
                mx1 = fmaxf(mx1, __shfl_xor_sync(0xffffffffu, mx1, m));
            }
            float mn0 = fmaxf(mm[mi][0], mx0);
            float mn1 = fmaxf(mm[mi][1], mx1);
            float c0 = __expf(mm[mi][0] - mn0);
            float c1 = __expf(mm[mi][1] - mn1);
            mm[mi][0] = mn0; mm[mi][1] = mn1;
            ll[mi][0] *= c0; ll[mi][1] *= c1;
            #pragma unroll
            for (int n = 0; n < 8; n++) {
                o[mi][n][0] *= c0; o[mi][n][1] *= c0;
                o[mi][n][2] *= c1; o[mi][n][3] *= c1;
            }
            #pragma unroll
            for (int n = 0; n < 8; n++) {
                sc[mi][n][0] = __expf(sc[mi][n][0] - mn0);
                sc[mi][n][1] = __expf(sc[mi][n][1] - mn0);
                sc[mi][n][2] = __expf(sc[mi][n][2] - mn1);
                sc[mi][n][3] = __expf(sc[mi][n][3] - mn1);
                ll[mi][0] += sc[mi][n][0] + sc[mi][n][1];
                ll[mi][1] += sc[mi][n][2] + sc[mi][n][3];
            }
            // round P to tf32 (RNA) before it becomes an mma operand
            #pragma unroll
            for (int n = 0; n < 8; n++)
                #pragma unroll
                for (int c = 0; c < 4; c++)
                    sc[mi][n][c] = to_tf32(sc[mi][n][c]);
        }

        // ---- O += P V, P permuted C-frag -> A-frag via quad shuffles ----
        #pragma unroll
        for (int kk = 0; kk < 8; kk++) {
            float pa[2][4];
            #pragma unroll
            for (int mi = 0; mi < 2; mi++) {
                float e0a = __shfl_sync(0xffffffffu, sc[mi][kk][0], src);
                float e0b = __shfl_sync(0xffffffffu, sc[mi][kk][1], src);
                float e1a = __shfl_sync(0xffffffffu, sc[mi][kk][2], src);
                float e1b = __shfl_sync(0xffffffffu, sc[mi][kk][3], src);
                float e2a = __shfl_sync(0xffffffffu, sc[mi][kk][0], src2);
                float e2b = __shfl_sync(0xffffffffu, sc[mi][kk][1], src2);
                float e3a = __shfl_sync(0xffffffffu, sc[mi][kk][2], src2);
                float e3b = __shfl_sync(0xffffffffu, sc[mi][kk][3], src2);
                pa[mi][0] = (lc & 1) ? e0b : e0a;
                pa[mi][1] = (lc & 1) ? e1b : e1a;
                pa[mi][2] = (lc & 1) ? e2b : e2a;
                pa[mi][3] = (lc & 1) ? e3b : e3a;
            }
            #pragma unroll
            for (int n = 0; n < 8; n++) {
                float b0 = vb[(kk * 8 + lc    ) * AS_STR + n * 8 + lr];
                float b1 = vb[(kk * 8 + lc + 4) * AS_STR + n * 8 + lr];
                mma16n8k8(o[0][n], pa[0], b0, b1);
                mma16n8k8(o[1][n], pa[1], b0, b1);
            }
        }
        __syncthreads();
    }

    // ---- finalize ----
    #pragma unroll
    for (int mi = 0; mi < 2; mi++)
        #pragma unroll
        for (int half = 0; half < 2; half++)
            #pragma unroll
            for (int m = 1; m <= 2; m <<= 1)
                ll[mi][half] += __shfl_xor_sync(0xffffffffu, ll[mi][half], m);

    const int bb = bh / HH;
    const int hh = bh % HH;
    #pragma unroll
    for (int mi = 0; mi < 2; mi++) {
        #pragma unroll
        for (int half = 0; half < 2; half++) {
            float inv = 1.f / ll[mi][half];
            int row = qt0 + warp * 32 + mi * 16 + lr + half * 8;
            float* og = g_attn + ((size_t)bb * TT + row) * DD + hh * HS;
            #pragma unroll
            for (int n = 0; n < 8; n++) {
                *(float2*)(og + n * 8 + 2 * lc) =
                    make_float2(to_tf32(o[mi][n][half * 2]     * inv),
                                to_tf32(o[mi][n][half * 2 + 1] * inv));
            }
        }
    }
}

// ---------------------------------------------------------------------------
// Kernel 3: output projection, tf32 mma + cp.async double buffer.
// grid (BT/128=64, D/64=8), block 128. Warp: 32 rows x 64 cols.
// ---------------------------------------------------------------------------
__global__ __launch_bounds__(128, 4) void oproj_mma_kernel(
    const float* __restrict__ bo,
    float* __restrict__ out)
{
    extern __shared__ float sm[];
    float* xs = sm;
    float* ws = sm + 2 * XS_BUF;

    const int tid  = threadIdx.x;
    const int lane = tid & 31;
    const int warp = tid >> 5;
    const int lr   = lane >> 2;
    const int lc   = lane & 3;
    const int m0   = blockIdx.x * 128;
    const int n0   = blockIdx.y * 64;

    const float* X = g_attn;
    const float* W = g_wo + n0;

    const uint32_t xs_s = (uint32_t)__cvta_generic_to_shared(xs);
    const uint32_t ws_s = (uint32_t)__cvta_generic_to_shared(ws);

    const int xr = tid >> 3, xc4 = tid & 7;
    const int wk = tid >> 4, we4 = tid & 15;

    #define OP_ISSUE(chunk, buf) do {                                           \
        int k0_ = (chunk) * 32;                                                 \
        _Pragma("unroll")                                                       \
        for (int it = 0; it < 8; it++) {                                        \
            int r = xr + it * 16;                                               \
            cpa16(xs_s + ((buf) * XS_BUF + r * XS_STR + xc4 * 4) * 4,           \
                  X + (size_t)(m0 + r) * DD + k0_ + xc4 * 4);                   \
        }                                                                       \
        _Pragma("unroll")                                                       \
        for (int it = 0; it < 4; it++) {                                        \
            int kk = wk + it * 8;                                               \
            cpa16(ws_s + ((buf) * WS_BUF + kk * WS_STR + we4 * 4) * 4,          \
                  W + (size_t)(k0_ + kk) * DD + we4 * 4);                       \
        }                                                                       \
    } while (0)

    float acc[2][8][4];
    #pragma unroll
    for (int mi = 0; mi < 2; mi++)
        #pragma unroll
        for (int n = 0; n < 8; n++)
            #pragma unroll
            for (int c = 0; c < 4; c++) acc[mi][n][c] = 0.f;

    OP_ISSUE(0, 0);
    cpa_commit();

    for (int c = 0; c < 16; c++) {
        int cur = c & 1;
        if (c < 15) { OP_ISSUE(c + 1, cur ^ 1); cpa_commit(); cpa_wait1(); }
        else        { cpa_wait0(); }
        __syncthreads();

        const float* xb = xs + cur * XS_BUF;
        const float* wb = ws + cur * WS_BUF;
        #pragma unroll
        for (int kk = 0; kk < 4; kk++) {
            float a[2][4];
            #pragma unroll
            for (int mi = 0; mi < 2; mi++) {
                int row = warp * 32 + mi * 16;
                a[mi][0] = xb[(row + lr    ) * XS_STR + kk * 8 + lc    ];
                a[mi][1] = xb[(row + lr + 8) * XS_STR + kk * 8 + lc    ];
                a[mi][2] = xb[(row + lr    ) * XS_STR + kk * 8 + lc + 4];
                a[mi][3] = xb[(row + lr + 8) * XS_STR + kk * 8 + lc + 4];
            }
            #pragma unroll
            for (int n = 0; n < 8; n++) {
                float b0 = wb[(kk * 8 + lc    ) * WS_STR + n * 8 + lr];
                float b1 = wb[(kk * 8 + lc + 4) * WS_STR + n * 8 + lr];
                mma16n8k8(acc[0][n], a[0], b0, b1);
                mma16n8k8(acc[1][n], a[1], b0, b1);
            }
        }
        __syncthreads();
    }

    #pragma unroll
    for (int mi = 0; mi < 2; mi++) {
        #pragma unroll
        for (int half = 0; half < 2; half++) {
            int m = m0 + warp * 32 + mi * 16 + lr + half * 8;
            float* og = out + (size_t)m * DD + n0;
            #pragma unroll
            for (int n = 0; n < 8; n++) {
                float2 bias = *(const float2*)(bo + n0 + n * 8 + 2 * lc);
                *(float2*)(og + n * 8 + 2 * lc) =
                    make_float2(acc[mi][n][half * 2]     + bias.x,
                                acc[mi][n][half * 2 + 1] + bias.y);
            }
        }
    }
}

// ---------------------------------------------------------------------------
extern "C" void kernel_launch(void* const* d_in, const int* in_sizes, int n_in,
                              void* d_out, int out_size)
{
    const float* x  = (const float*)d_in[0];
    const float* Wq = (const float*)d_in[1];
    const float* Wk = (const float*)d_in[2];
    const float* Wv = (const float*)d_in[3];
    const float* Wo = (const float*)d_in[4];
    const float* bo = (const float*)d_in[5];
    float* out = (float*)d_out;

    static bool attr_done = false;
    if (!attr_done) {
        cudaFuncSetAttribute(qkv_mma_kernel,
            cudaFuncAttributeMaxDynamicSharedMemorySize, 2*(XS_BUF+WS_BUF)*4);
        cudaFuncSetAttribute(attn_mma_kernel,
            cudaFuncAttributeMaxDynamicSharedMemorySize, (Q_BUF+4*KV_BUF)*4);
        cudaFuncSetAttribute(oproj_mma_kernel,
            cudaFuncAttributeMaxDynamicSharedMemorySize, 2*(XS_BUF+WS_BUF)*4);
        attr_done = true;
    }

    round_x_kernel<<<(BB*TT*DD/4)/256, 256>>>(x);
    dim3 gw((HH*DD*HS/4)/256, 4);
    round_w_kernel<<<gw, 256>>>(Wq, Wk, Wv, Wo);

    dim3 g1((BB * TT) / 128, HH, 3);
    qkv_mma_kernel<<<g1, 128, 2*(XS_BUF+WS_BUF)*4>>>();

    dim3 g2(TT / 128, BB * HH);
    attn_mma_kernel<<<g2, 128, (Q_BUF+4*KV_BUF)*4>>>();

    dim3 g3((BB * TT) / 128, DD / 64);
    oproj_mma_kernel<<<g3, 128, 2*(XS_BUF+WS_BUF)*4>>>(bo, out);
}